// round 2
// baseline (speedup 1.0000x reference)
#include <cuda_runtime.h>
#include <math.h>

#define TOTP 500000
#define BATCH 64
#define KTOT 398
#define CLIP0 1.0f
#define CLIP1 1.0f

// ---------------- scratch (device globals; no allocations) ----------------
__device__ float g_E[BATCH * KTOT];           // embeddings [64][398]
__device__ float g_rsq[BATCH];                // per-row residual sum of squares
__device__ __align__(16) float g_resid[(size_t)BATCH * TOTP]; // residual scratch, 128 MB

// ---------------- f32x2 helpers ----------------
__device__ __forceinline__ unsigned long long ffma2(unsigned long long a,
                                                    unsigned long long b,
                                                    unsigned long long c) {
    unsigned long long d;
    asm("fma.rn.f32x2 %0, %1, %2, %3;" : "=l"(d) : "l"(a), "l"(b), "l"(c));
    return d;
}
__device__ __forceinline__ unsigned long long pack2(float x, float y) {
    unsigned long long d;
    asm("mov.b64 %0, {%1, %2};" : "=l"(d) : "f"(x), "f"(y));
    return d;
}
__device__ __forceinline__ float2 unpack2(unsigned long long v) {
    float2 r;
    asm("mov.b64 {%0, %1}, %2;" : "=f"(r.x), "=f"(r.y) : "l"(v));
    return r;
}

// ---------------- init ----------------
__global__ void k_init() {
    int t = blockIdx.x * blockDim.x + threadIdx.x;
    if (t < BATCH * KTOT) g_E[t] = 0.0f;
    if (t < BATCH) g_rsq[t] = 0.0f;
}

// ---------------- GEMM1: E[b][c] += sum_p G[b][pbase+p] * Bm[p][c] ----------------
// Block tile: 64 (batch) x (NT2*32) (cols, padded), split-K over P in chunks.
// 256 threads = 16x16; thread tile = 4 rows x NT2 col-pairs (f32x2).
template <int NT2>
__global__ __launch_bounds__(256) void k_gemm1(
    const float* __restrict__ G, const float* __restrict__ Bm,
    int numP, int pbase, int KG, int koff, int chunk)
{
    constexpr int PADK = NT2 * 32;
    __shared__ float Gs[32][65];       // [k][b], padded to kill bank conflicts
    __shared__ float Bs[32][PADK];     // [k][c]

    const int tid = threadIdx.x;
    const int ty = tid >> 4;           // 0..15 -> rows ty*4 .. ty*4+3
    const int tx = tid & 15;           // 0..15 -> col-pairs tx + 16*j

    const int pstart = blockIdx.x * chunk;
    const int pend   = min(pstart + chunk, numP);

    unsigned long long acc[4][NT2];
#pragma unroll
    for (int i = 0; i < 4; i++)
#pragma unroll
        for (int j = 0; j < NT2; j++) acc[i][j] = 0ULL;

    for (int pt = pstart; pt < pend; pt += 32) {
        // stage G tile: Gs[pp][b] = G[b][pbase + pt + pp]
        {
            const int pp = tid & 31;
            const int b0 = tid >> 5;           // 0..7
            const int p  = pt + pp;
            const bool ok = (p < pend);
#pragma unroll
            for (int i = 0; i < 8; i++) {
                const int b = b0 + i * 8;
                Gs[pp][b] = ok ? G[(size_t)b * TOTP + pbase + p] : 0.0f;
            }
        }
        // stage B tile: Bs[r][c] = Bm[(pt+r)][c], zero-padded
        for (int idx = tid; idx < 32 * PADK; idx += 256) {
            const int r = idx / PADK;
            const int c = idx - r * PADK;
            const int prow = pt + r;
            float v = 0.0f;
            if (c < KG && prow < pend) v = Bm[(size_t)prow * KG + c];
            Bs[r][c] = v;
        }
        __syncthreads();

#pragma unroll
        for (int kk = 0; kk < 32; kk++) {
            unsigned long long a2[4], b2[NT2];
#pragma unroll
            for (int i = 0; i < 4; i++) {
                const float a = Gs[kk][ty * 4 + i];
                a2[i] = pack2(a, a);
            }
#pragma unroll
            for (int j = 0; j < NT2; j++)
                b2[j] = *(const unsigned long long*)&Bs[kk][2 * (tx + 16 * j)];
#pragma unroll
            for (int i = 0; i < 4; i++)
#pragma unroll
                for (int j = 0; j < NT2; j++)
                    acc[i][j] = ffma2(a2[i], b2[j], acc[i][j]);
        }
        __syncthreads();
    }

    // epilogue: atomic accumulate into tiny E
#pragma unroll
    for (int i = 0; i < 4; i++) {
        const int b = ty * 4 + i;
#pragma unroll
        for (int j = 0; j < NT2; j++) {
            const float2 v = unpack2(acc[i][j]);
            const int c = 2 * (tx + 16 * j);
            if (c < KG)     atomicAdd(&g_E[b * KTOT + koff + c],     v.x);
            if (c + 1 < KG) atomicAdd(&g_E[b * KTOT + koff + c + 1], v.y);
        }
    }
}

// ---------------- embed clip + average -> out[0..397] ----------------
__global__ void k_embed(float* __restrict__ out) {
    __shared__ float scale[BATCH];
    const int tid = threadIdx.x;
    if (tid < BATCH) {
        float s = 0.0f;
        for (int j = 0; j < KTOT; j++) {
            const float v = g_E[tid * KTOT + j];
            s += v * v;
        }
        const float n = sqrtf(s);
        const float sc = (n > CLIP0) ? (CLIP0 / n) : 1.0f;
        scale[tid] = sc * (1.0f / BATCH);
    }
    __syncthreads();
    for (int j = tid; j < KTOT; j += blockDim.x) {
        float s = 0.0f;
        for (int b = 0; b < BATCH; b++) s += g_E[b * KTOT + j] * scale[b];
        out[j] = s;
    }
}

// ---------------- GEMM2 + residual + stats ----------------
// approx[b][p] = sum_j E[b][j]*Bm[p][j];  residual = G - approx -> scratch
// also: per-row sum(res^2) -> g_rsq (atomic), colsum(G)/64 -> avg_target segment
// Block tile: 64 (batch) x 128 (p). 256 threads = 16x16; thread = 4 rows x 4 p-pairs.
template <int KGP>   // K padded to multiple of 8
__global__ __launch_bounds__(256) void k_gemm2(
    const float* __restrict__ G, const float* __restrict__ Bm,
    float* __restrict__ out_target, int numP, int pbase, int KG, int koff, int ntiles)
{
    __shared__ float Es[BATCH][KGP];
    __shared__ float Bs[8][130];       // [j][p], transposed stage for p-pair packing
    __shared__ float colsum[128];

    const int tid = threadIdx.x;
    const int ty = tid >> 4;
    const int tx = tid & 15;

    // load E slice for this group (zero-pad j >= KG)
    for (int idx = tid; idx < BATCH * KGP; idx += 256) {
        const int b = idx / KGP;
        const int j = idx - b * KGP;
        Es[b][j] = (j < KG) ? g_E[b * KTOT + koff + j] : 0.0f;
    }

    float rs[4] = {0.f, 0.f, 0.f, 0.f};

    for (int tile = blockIdx.x; tile < ntiles; tile += gridDim.x) {
        const int p0 = tile * 128;
        unsigned long long acc[4][4];
#pragma unroll
        for (int i = 0; i < 4; i++)
#pragma unroll
            for (int q = 0; q < 4; q++) acc[i][q] = 0ULL;

        for (int kt = 0; kt < KGP; kt += 8) {
            __syncthreads();   // protects Bs reuse; first one also orders Es load
            // stage Bs[jj][pp] = Bm[(p0+pp)][kt+jj]
            {
                const int jj  = tid & 7;
                const int ppb = tid >> 3;       // 0..31
                const int j   = kt + jj;
#pragma unroll
                for (int r = 0; r < 4; r++) {
                    const int pp = ppb + r * 32;
                    const int p  = p0 + pp;
                    float v = 0.0f;
                    if (p < numP && j < KG) v = Bm[(size_t)p * KG + j];
                    Bs[jj][pp] = v;
                }
            }
            __syncthreads();
#pragma unroll
            for (int jj = 0; jj < 8; jj++) {
                const int j = kt + jj;
                unsigned long long a2[4], b2[4];
#pragma unroll
                for (int i = 0; i < 4; i++) {
                    const float a = Es[ty * 4 + i][j];
                    a2[i] = pack2(a, a);
                }
#pragma unroll
                for (int q = 0; q < 4; q++)
                    b2[q] = *(const unsigned long long*)&Bs[jj][2 * (tx + 16 * q)];
#pragma unroll
                for (int i = 0; i < 4; i++)
#pragma unroll
                    for (int q = 0; q < 4; q++)
                        acc[i][q] = ffma2(a2[i], b2[q], acc[i][q]);
            }
        }

        // epilogue: residual, rsq, colsum
        if (tid < 128) colsum[tid] = 0.0f;
        __syncthreads();
#pragma unroll
        for (int q = 0; q < 4; q++) {
            const int pp = 2 * (tx + 16 * q);
            const int p  = p0 + pp;
            float2 cs = make_float2(0.f, 0.f);
#pragma unroll
            for (int i = 0; i < 4; i++) {
                const int b = ty * 4 + i;
                float2 gv = make_float2(0.f, 0.f);
                if (p < numP)
                    gv = *(const float2*)&G[(size_t)b * TOTP + pbase + p];
                const float2 a = unpack2(acc[i][q]);
                const float2 r = make_float2(gv.x - a.x, gv.y - a.y);
                if (p < numP)
                    *(float2*)&g_resid[(size_t)b * TOTP + pbase + p] = r;
                rs[i] += r.x * r.x + r.y * r.y;
                cs.x += gv.x; cs.y += gv.y;
            }
            atomicAdd(&colsum[pp],     cs.x);
            atomicAdd(&colsum[pp + 1], cs.y);
        }
        __syncthreads();
        if (tid < 128) {
            const int p = p0 + tid;
            if (p < numP) out_target[p] = colsum[tid] * (1.0f / BATCH);
        }
    }

    // reduce rsq across the 16 tx lanes of each ty group
#pragma unroll
    for (int i = 0; i < 4; i++) {
        float v = rs[i];
#pragma unroll
        for (int off = 8; off > 0; off >>= 1)
            v += __shfl_xor_sync(0xffffffffu, v, off, 16);
        if (tx == 0) atomicAdd(&g_rsq[ty * 4 + i], v);
    }
}

// ---------------- final: clipped residual average -> out[398 .. 398+TOTP) ----------------
// NOTE: out + 398 floats is 8-byte (not 16-byte) aligned -> stores must be float2.
__global__ __launch_bounds__(256) void k_final(float* __restrict__ out_resid) {
    __shared__ float scale[BATCH];
    const int tid = threadIdx.x;
    if (tid < BATCH) {
        const float n = sqrtf(g_rsq[tid]);
        scale[tid] = ((n > CLIP1) ? (CLIP1 / n) : 1.0f) * (1.0f / BATCH);
    }
    __syncthreads();
    const int p4 = blockIdx.x * blockDim.x + tid;   // float4 index
    if (p4 < TOTP / 4) {
        float4 s = make_float4(0.f, 0.f, 0.f, 0.f);
#pragma unroll 4
        for (int b = 0; b < BATCH; b++) {
            const float4 r = *(const float4*)&g_resid[(size_t)b * TOTP + p4 * 4];
            const float sc = scale[b];
            s.x += r.x * sc; s.y += r.y * sc; s.z += r.z * sc; s.w += r.w * sc;
        }
        // two float2 stores: (398 + 4*p4) is even -> 8B aligned; +2 also even.
        *(float2*)&out_resid[p4 * 4]     = make_float2(s.x, s.y);
        *(float2*)&out_resid[p4 * 4 + 2] = make_float2(s.z, s.w);
    }
}

// ---------------- launch ----------------
extern "C" void kernel_launch(void* const* d_in, const int* in_sizes, int n_in,
                              void* d_out, int out_size) {
    (void)in_sizes; (void)n_in; (void)out_size;
    const float* G  = (const float*)d_in[0];
    const float* B0 = (const float*)d_in[1];
    const float* B1 = (const float*)d_in[2];
    const float* B2 = (const float*)d_in[3];
    float* out = (float*)d_out;

    k_init<<<100, 256>>>();

    const int chunk = 512;
    k_gemm1<4><<<(100000 + chunk - 1) / chunk, 256>>>(G, B0, 100000,      0, 104,   0, chunk);
    k_gemm1<5><<<(225000 + chunk - 1) / chunk, 256>>>(G, B1, 225000, 100000, 156, 104, chunk);
    k_gemm1<5><<<(175000 + chunk - 1) / chunk, 256>>>(G, B2, 175000, 325000, 138, 260, chunk);

    k_embed<<<1, 256>>>(out);

    // out layout: [0,398) embed | [398, 398+500000) residual | then target avg
    float* out_tg = out + 398 + TOTP;
    {
        const int nt0 = (100000 + 127) / 128;   // 782
        const int nt1 = (225000 + 127) / 128;   // 1758
        const int nt2 = (175000 + 127) / 128;   // 1368
        k_gemm2<104><<<nt0, 256>>>(G, B0, out_tg +      0, 100000,      0, 104,   0, nt0);
        k_gemm2<160><<<1184, 256>>>(G, B1, out_tg + 100000, 225000, 100000, 156, 104, nt1);
        k_gemm2<144><<<1184, 256>>>(G, B2, out_tg + 325000, 175000, 325000, 138, 260, nt2);
    }

    k_final<<<(TOTP / 4 + 255) / 256, 256>>>(out + 398);
}

// round 3
// speedup vs baseline: 1.0059x; 1.0059x over previous
#include <cuda_runtime.h>
#include <math.h>

#define TOTP 500000
#define BATCH 64
#define KTOT 398
#define CLIP0 1.0f
#define CLIP1 1.0f

// ---------------- scratch (device globals; no allocations) ----------------
__device__ float g_E[BATCH * KTOT];           // embeddings [64][398]
__device__ float g_rsq[BATCH];                // per-row residual sum of squares
__device__ __align__(16) float g_resid[(size_t)BATCH * TOTP]; // residual scratch, 128 MB

// ---------------- f32x2 helpers ----------------
__device__ __forceinline__ unsigned long long ffma2(unsigned long long a,
                                                    unsigned long long b,
                                                    unsigned long long c) {
    unsigned long long d;
    asm("fma.rn.f32x2 %0, %1, %2, %3;" : "=l"(d) : "l"(a), "l"(b), "l"(c));
    return d;
}
__device__ __forceinline__ unsigned long long pack2(float x, float y) {
    unsigned long long d;
    asm("mov.b64 %0, {%1, %2};" : "=l"(d) : "f"(x), "f"(y));
    return d;
}
__device__ __forceinline__ float2 unpack2(unsigned long long v) {
    float2 r;
    asm("mov.b64 {%0, %1}, %2;" : "=f"(r.x), "=f"(r.y) : "l"(v));
    return r;
}

// ---------------- init ----------------
__global__ void k_init() {
    int t = blockIdx.x * blockDim.x + threadIdx.x;
    if (t < BATCH * KTOT) g_E[t] = 0.0f;
    if (t < BATCH) g_rsq[t] = 0.0f;
}

// ---------------- GEMM1: E[b][c] += sum_p G[b][pbase+p] * Bm[p][c] ----------------
// Block tile: 64 (batch) x (NT2*32) (cols, padded), split-K over P in chunks.
// 256 threads = 16x16; thread tile = 4 rows x NT2 col-pairs (f32x2).
template <int NT2>
__global__ __launch_bounds__(256) void k_gemm1(
    const float* __restrict__ G, const float* __restrict__ Bm,
    int numP, int pbase, int KG, int koff, int chunk)
{
    constexpr int PADK = NT2 * 32;
    __shared__ float Gs[32][65];       // [k][b], padded to kill bank conflicts
    __shared__ float Bs[32][PADK];     // [k][c]

    const int tid = threadIdx.x;
    const int ty = tid >> 4;           // 0..15 -> rows ty*4 .. ty*4+3
    const int tx = tid & 15;           // 0..15 -> col-pairs tx + 16*j

    const int pstart = blockIdx.x * chunk;
    const int pend   = min(pstart + chunk, numP);

    unsigned long long acc[4][NT2];
#pragma unroll
    for (int i = 0; i < 4; i++)
#pragma unroll
        for (int j = 0; j < NT2; j++) acc[i][j] = 0ULL;

    for (int pt = pstart; pt < pend; pt += 32) {
        // stage G tile: Gs[pp][b] = G[b][pbase + pt + pp]
        {
            const int pp = tid & 31;
            const int b0 = tid >> 5;           // 0..7
            const int p  = pt + pp;
            const bool ok = (p < pend);
#pragma unroll
            for (int i = 0; i < 8; i++) {
                const int b = b0 + i * 8;
                Gs[pp][b] = ok ? G[(size_t)b * TOTP + pbase + p] : 0.0f;
            }
        }
        // stage B tile: Bs[r][c] = Bm[(pt+r)][c], zero-padded
        for (int idx = tid; idx < 32 * PADK; idx += 256) {
            const int r = idx / PADK;
            const int c = idx - r * PADK;
            const int prow = pt + r;
            float v = 0.0f;
            if (c < KG && prow < pend) v = Bm[(size_t)prow * KG + c];
            Bs[r][c] = v;
        }
        __syncthreads();

#pragma unroll
        for (int kk = 0; kk < 32; kk++) {
            unsigned long long a2[4], b2[NT2];
#pragma unroll
            for (int i = 0; i < 4; i++) {
                const float a = Gs[kk][ty * 4 + i];
                a2[i] = pack2(a, a);
            }
#pragma unroll
            for (int j = 0; j < NT2; j++)
                b2[j] = *(const unsigned long long*)&Bs[kk][2 * (tx + 16 * j)];
#pragma unroll
            for (int i = 0; i < 4; i++)
#pragma unroll
                for (int j = 0; j < NT2; j++)
                    acc[i][j] = ffma2(a2[i], b2[j], acc[i][j]);
        }
        __syncthreads();
    }

    // epilogue: atomic accumulate into tiny E
#pragma unroll
    for (int i = 0; i < 4; i++) {
        const int b = ty * 4 + i;
#pragma unroll
        for (int j = 0; j < NT2; j++) {
            const float2 v = unpack2(acc[i][j]);
            const int c = 2 * (tx + 16 * j);
            if (c < KG)     atomicAdd(&g_E[b * KTOT + koff + c],     v.x);
            if (c + 1 < KG) atomicAdd(&g_E[b * KTOT + koff + c + 1], v.y);
        }
    }
}

// ---------------- embed clip + average -> out[0..397] ----------------
__global__ void k_embed(float* __restrict__ out) {
    __shared__ float scale[BATCH];
    const int tid = threadIdx.x;
    if (tid < BATCH) {
        float s = 0.0f;
        for (int j = 0; j < KTOT; j++) {
            const float v = g_E[tid * KTOT + j];
            s += v * v;
        }
        const float n = sqrtf(s);
        const float sc = (n > CLIP0) ? (CLIP0 / n) : 1.0f;
        scale[tid] = sc * (1.0f / BATCH);
    }
    __syncthreads();
    for (int j = tid; j < KTOT; j += blockDim.x) {
        float s = 0.0f;
        for (int b = 0; b < BATCH; b++) s += g_E[b * KTOT + j] * scale[b];
        out[j] = s;
    }
}

// ---------------- GEMM2 + residual + stats ----------------
// approx[b][p] = sum_j E[b][j]*Bm[p][j];  residual = G - approx -> scratch
// also: per-row sum(res^2) -> g_rsq (atomic), colsum(G)/64 -> avg_target segment
// Block tile: 64 (batch) x 128 (p). 256 threads = 16x16; thread = 4 rows x 4 p-pairs.
template <int KGP>   // K padded to multiple of 8
__global__ __launch_bounds__(256) void k_gemm2(
    const float* __restrict__ G, const float* __restrict__ Bm,
    float* __restrict__ out_target, int numP, int pbase, int KG, int koff, int ntiles)
{
    __shared__ float Es[BATCH][KGP];
    __shared__ float Bs[8][130];       // [j][p], transposed stage for p-pair packing
    __shared__ float colsum[128];

    const int tid = threadIdx.x;
    const int ty = tid >> 4;
    const int tx = tid & 15;

    // load E slice for this group (zero-pad j >= KG)
    for (int idx = tid; idx < BATCH * KGP; idx += 256) {
        const int b = idx / KGP;
        const int j = idx - b * KGP;
        Es[b][j] = (j < KG) ? g_E[b * KTOT + koff + j] : 0.0f;
    }

    float rs[4] = {0.f, 0.f, 0.f, 0.f};

    for (int tile = blockIdx.x; tile < ntiles; tile += gridDim.x) {
        const int p0 = tile * 128;
        unsigned long long acc[4][4];
#pragma unroll
        for (int i = 0; i < 4; i++)
#pragma unroll
            for (int q = 0; q < 4; q++) acc[i][q] = 0ULL;

        for (int kt = 0; kt < KGP; kt += 8) {
            __syncthreads();   // protects Bs reuse; first one also orders Es load
            // stage Bs[jj][pp] = Bm[(p0+pp)][kt+jj]
            {
                const int jj  = tid & 7;
                const int ppb = tid >> 3;       // 0..31
                const int j   = kt + jj;
#pragma unroll
                for (int r = 0; r < 4; r++) {
                    const int pp = ppb + r * 32;
                    const int p  = p0 + pp;
                    float v = 0.0f;
                    if (p < numP && j < KG) v = Bm[(size_t)p * KG + j];
                    Bs[jj][pp] = v;
                }
            }
            __syncthreads();
#pragma unroll
            for (int jj = 0; jj < 8; jj++) {
                const int j = kt + jj;
                unsigned long long a2[4], b2[4];
#pragma unroll
                for (int i = 0; i < 4; i++) {
                    const float a = Es[ty * 4 + i][j];
                    a2[i] = pack2(a, a);
                }
#pragma unroll
                for (int q = 0; q < 4; q++)
                    b2[q] = *(const unsigned long long*)&Bs[jj][2 * (tx + 16 * q)];
#pragma unroll
                for (int i = 0; i < 4; i++)
#pragma unroll
                    for (int q = 0; q < 4; q++)
                        acc[i][q] = ffma2(a2[i], b2[q], acc[i][q]);
            }
        }

        // epilogue: residual, rsq, colsum
        if (tid < 128) colsum[tid] = 0.0f;
        __syncthreads();
#pragma unroll
        for (int q = 0; q < 4; q++) {
            const int pp = 2 * (tx + 16 * q);
            const int p  = p0 + pp;
            float2 cs = make_float2(0.f, 0.f);
#pragma unroll
            for (int i = 0; i < 4; i++) {
                const int b = ty * 4 + i;
                float2 gv = make_float2(0.f, 0.f);
                if (p < numP)
                    gv = *(const float2*)&G[(size_t)b * TOTP + pbase + p];
                const float2 a = unpack2(acc[i][q]);
                const float2 r = make_float2(gv.x - a.x, gv.y - a.y);
                if (p < numP)
                    *(float2*)&g_resid[(size_t)b * TOTP + pbase + p] = r;
                rs[i] += r.x * r.x + r.y * r.y;
                cs.x += gv.x; cs.y += gv.y;
            }
            atomicAdd(&colsum[pp],     cs.x);
            atomicAdd(&colsum[pp + 1], cs.y);
        }
        __syncthreads();
        if (tid < 128) {
            const int p = p0 + tid;
            if (p < numP) out_target[p] = colsum[tid] * (1.0f / BATCH);
        }
    }

    // reduce rsq across the 16 tx lanes of each ty group
#pragma unroll
    for (int i = 0; i < 4; i++) {
        float v = rs[i];
#pragma unroll
        for (int off = 8; off > 0; off >>= 1)
            v += __shfl_xor_sync(0xffffffffu, v, off, 16);
        if (tx == 0) atomicAdd(&g_rsq[ty * 4 + i], v);
    }
}

// ---------------- final: clipped residual average -> out[398 .. 398+TOTP) ----------------
// NOTE: out + 398 floats is 8-byte (not 16-byte) aligned -> stores must be float2.
__global__ __launch_bounds__(256) void k_final(float* __restrict__ out_resid) {
    __shared__ float scale[BATCH];
    const int tid = threadIdx.x;
    if (tid < BATCH) {
        const float n = sqrtf(g_rsq[tid]);
        scale[tid] = ((n > CLIP1) ? (CLIP1 / n) : 1.0f) * (1.0f / BATCH);
    }
    __syncthreads();
    const int p4 = blockIdx.x * blockDim.x + tid;   // float4 index
    if (p4 < TOTP / 4) {
        float4 s = make_float4(0.f, 0.f, 0.f, 0.f);
#pragma unroll 4
        for (int b = 0; b < BATCH; b++) {
            const float4 r = *(const float4*)&g_resid[(size_t)b * TOTP + p4 * 4];
            const float sc = scale[b];
            s.x += r.x * sc; s.y += r.y * sc; s.z += r.z * sc; s.w += r.w * sc;
        }
        // two float2 stores: (398 + 4*p4) is even -> 8B aligned; +2 also even.
        *(float2*)&out_resid[p4 * 4]     = make_float2(s.x, s.y);
        *(float2*)&out_resid[p4 * 4 + 2] = make_float2(s.z, s.w);
    }
}

// ---------------- launch ----------------
extern "C" void kernel_launch(void* const* d_in, const int* in_sizes, int n_in,
                              void* d_out, int out_size) {
    (void)in_sizes; (void)n_in; (void)out_size;
    const float* G  = (const float*)d_in[0];
    const float* B0 = (const float*)d_in[1];
    const float* B1 = (const float*)d_in[2];
    const float* B2 = (const float*)d_in[3];
    float* out = (float*)d_out;

    k_init<<<100, 256>>>();

    const int chunk = 512;
    k_gemm1<4><<<(100000 + chunk - 1) / chunk, 256>>>(G, B0, 100000,      0, 104,   0, chunk);
    k_gemm1<5><<<(225000 + chunk - 1) / chunk, 256>>>(G, B1, 225000, 100000, 156, 104, chunk);
    k_gemm1<5><<<(175000 + chunk - 1) / chunk, 256>>>(G, B2, 175000, 325000, 138, 260, chunk);

    k_embed<<<1, 256>>>(out);

    // out layout: [0,398) embed | [398, 398+500000) residual | then target avg
    float* out_tg = out + 398 + TOTP;
    {
        const int nt0 = (100000 + 127) / 128;   // 782
        const int nt1 = (225000 + 127) / 128;   // 1758
        const int nt2 = (175000 + 127) / 128;   // 1368
        k_gemm2<104><<<nt0, 256>>>(G, B0, out_tg +      0, 100000,      0, 104,   0, nt0);
        k_gemm2<160><<<1184, 256>>>(G, B1, out_tg + 100000, 225000, 100000, 156, 104, nt1);
        k_gemm2<144><<<1184, 256>>>(G, B2, out_tg + 325000, 175000, 325000, 138, 260, nt2);
    }

    k_final<<<(TOTP / 4 + 255) / 256, 256>>>(out + 398);
}